// round 1
// baseline (speedup 1.0000x reference)
#include <cuda_runtime.h>
#include <cstdint>

// ---------------------------------------------------------------------------
// Performer causal linear attention, fp32.
// b=2 h=8 n=4096 d=64 r=256 chunk=64  -> 65536 tokens, 1024 chunks ("tiles")
//
// Pipeline:
//   k_prep   : projT[k][r] = proj[r][k]*d^-0.25 ; reset global max key
//   k_feat<Q>: qp = ratio*(exp(dash - diag - rowmax)+1e-4)        -> g_qp
//   k_feat<K>: store adj = dash - diag; atomicMax global max(dash) -> g_kf
//   k_chunk  : kp = ratio*(exp(adj - stab)+1e-4) in place; per-chunk
//              S_c = kp^T v  [256x64], z_c = sum kp [256]          -> g_sums
//   k_scan   : exclusive prefix over the 64 chunks of each head (in place)
//   k_out    : out = (Q@S_pre + causalmask(Q K^T) @ V) * Dinv
// ---------------------------------------------------------------------------

constexpr int D_ = 64;
constexpr int R_ = 256;
constexpr int C_ = 64;
constexpr int NTILES = 1024;                 // 65536 tokens / 64
constexpr int SSTRIDE = R_ * D_ + R_;        // 16640 floats per chunk record

__device__ __align__(16) float g_projT[D_ * R_];
__device__ __align__(16) float g_qp[(size_t)NTILES * C_ * R_];
__device__ __align__(16) float g_kf[(size_t)NTILES * C_ * R_];
__device__ __align__(16) float g_sums[(size_t)NTILES * SSTRIDE];
__device__ unsigned g_maxkey;

#define NORM_F   0.35355339059327373f   /* 64^-0.25 */
#define DIAGC_F  0.0625f                /* 0.5 * 64^-0.5 */
#define RATIO_F  0.0625f                /* 256^-0.5 */
#define KEPS_F   1e-4f
#define AEPS_F   1e-6f

// fast e^x via exp2 polynomial (FFMA pipe only; avoids MUFU.EX2 throughput wall)
__device__ __forceinline__ float fexp(float x) {
    x = fmaxf(x, -87.0f);
    float t  = x * 1.4426950408889634f;
    float nf = rintf(t);
    float f  = t - nf;
    float p  = 1.5403530393e-4f;
    p = fmaf(p, f, 1.3333558146e-3f);
    p = fmaf(p, f, 9.6181291076e-3f);
    p = fmaf(p, f, 5.5504108665e-2f);
    p = fmaf(p, f, 2.4022650696e-1f);
    p = fmaf(p, f, 6.9314718056e-1f);
    p = fmaf(p, f, 1.0f);
    int n = (int)nf;
    return p * __int_as_float((n + 127) << 23);
}

// monotonic float<->unsigned for atomicMax over signed floats
__device__ __forceinline__ unsigned fkey(float f) {
    unsigned u = __float_as_uint(f);
    return (u & 0x80000000u) ? ~u : (u | 0x80000000u);
}
__device__ __forceinline__ float fdec(unsigned k) {
    return (k & 0x80000000u) ? __uint_as_float(k ^ 0x80000000u)
                             : __uint_as_float(~k);
}

// ---------------------------------------------------------------------------
__global__ void k_prep(const float* __restrict__ proj) {
    int tid = threadIdx.x;
    for (int idx = tid; idx < D_ * R_; idx += blockDim.x) {
        int kk = idx / R_, rr = idx % R_;
        g_projT[idx] = proj[rr * D_ + kk] * NORM_F;
    }
    if (tid == 0) g_maxkey = 0u;
}

// ---------------------------------------------------------------------------
// Feature map: one block per 64-token tile. dash[t][r] = sum_k x[t][k]*projT[k][r]
template <bool ISQ>
__global__ void __launch_bounds__(256) k_feat(const float* __restrict__ x) {
    extern __shared__ float sm[];
    float* pT   = sm;                     // [64][256]
    float* xT   = sm + D_ * R_;           // [64][65] transposed x tile (pad 65)
    float* dg   = xT + 64 * 65;           // [64] diag
    float* wred = dg + 64;                // [8]
    const int tile = blockIdx.x, tid = threadIdx.x;
    const float* xg = x + (size_t)tile * (C_ * D_);
    float* dstT = (ISQ ? g_qp : g_kf) + (size_t)tile * (C_ * R_);

#pragma unroll
    for (int i = 0; i < 16; i++) {
        int i4 = tid + i * 256;
        reinterpret_cast<float4*>(pT)[i4] =
            reinterpret_cast<const float4*>(g_projT)[i4];
    }
#pragma unroll
    for (int i = 0; i < 16; i++) {
        int idx = tid + i * 256;
        xT[(idx & 63) * 65 + (idx >> 6)] = xg[idx];
    }
    __syncthreads();
    if (tid < 64) {
        float s = 0.f;
#pragma unroll
        for (int kk = 0; kk < 64; kk++) {
            float vv = xT[kk * 65 + tid];
            s = fmaf(vv, vv, s);
        }
        dg[tid] = DIAGC_F * s;
    }
    __syncthreads();

    const int tg = tid >> 4, rg = tid & 15;
    float acc[4][16];
#pragma unroll
    for (int i = 0; i < 4; i++)
#pragma unroll
        for (int j = 0; j < 16; j++) acc[i][j] = 0.f;

#pragma unroll 8
    for (int kk = 0; kk < 64; kk++) {
        float a0 = xT[kk * 65 + tg * 4 + 0];
        float a1 = xT[kk * 65 + tg * 4 + 1];
        float a2 = xT[kk * 65 + tg * 4 + 2];
        float a3 = xT[kk * 65 + tg * 4 + 3];
        float bb[16];
#pragma unroll
        for (int jj = 0; jj < 4; jj++) {
            float4 b4 = *reinterpret_cast<const float4*>(pT + kk * R_ + jj * 64 + rg * 4);
            bb[4 * jj + 0] = b4.x; bb[4 * jj + 1] = b4.y;
            bb[4 * jj + 2] = b4.z; bb[4 * jj + 3] = b4.w;
        }
#pragma unroll
        for (int j = 0; j < 16; j++) {
            acc[0][j] = fmaf(a0, bb[j], acc[0][j]);
            acc[1][j] = fmaf(a1, bb[j], acc[1][j]);
            acc[2][j] = fmaf(a2, bb[j], acc[2][j]);
            acc[3][j] = fmaf(a3, bb[j], acc[3][j]);
        }
    }

    if (ISQ) {
#pragma unroll
        for (int i = 0; i < 4; i++) {
            float m = acc[i][0];
#pragma unroll
            for (int j = 1; j < 16; j++) m = fmaxf(m, acc[i][j]);
#pragma unroll
            for (int off = 1; off < 16; off <<= 1)
                m = fmaxf(m, __shfl_xor_sync(0xffffffffu, m, off, 16));
            const float dgi = dg[tg * 4 + i];
            float* rowp = dstT + (tg * 4 + i) * R_;
#pragma unroll
            for (int jj = 0; jj < 4; jj++) {
                float4 o;
                o.x = RATIO_F * (fexp(acc[i][4 * jj + 0] - dgi - m) + KEPS_F);
                o.y = RATIO_F * (fexp(acc[i][4 * jj + 1] - dgi - m) + KEPS_F);
                o.z = RATIO_F * (fexp(acc[i][4 * jj + 2] - dgi - m) + KEPS_F);
                o.w = RATIO_F * (fexp(acc[i][4 * jj + 3] - dgi - m) + KEPS_F);
                *reinterpret_cast<float4*>(rowp + jj * 64 + rg * 4) = o;
            }
        }
    } else {
        float m = -3.0e38f;
#pragma unroll
        for (int i = 0; i < 4; i++)
#pragma unroll
            for (int j = 0; j < 16; j++) m = fmaxf(m, acc[i][j]);
#pragma unroll
        for (int off = 16; off >= 1; off >>= 1)
            m = fmaxf(m, __shfl_xor_sync(0xffffffffu, m, off));
        if ((tid & 31) == 0) wred[tid >> 5] = m;
#pragma unroll
        for (int i = 0; i < 4; i++) {
            const float dgi = dg[tg * 4 + i];
            float* rowp = dstT + (tg * 4 + i) * R_;
#pragma unroll
            for (int jj = 0; jj < 4; jj++) {
                float4 o;
                o.x = acc[i][4 * jj + 0] - dgi;
                o.y = acc[i][4 * jj + 1] - dgi;
                o.z = acc[i][4 * jj + 2] - dgi;
                o.w = acc[i][4 * jj + 3] - dgi;
                *reinterpret_cast<float4*>(rowp + jj * 64 + rg * 4) = o;
            }
        }
        __syncthreads();
        if (tid == 0) {
            float mm = wred[0];
#pragma unroll
            for (int w = 1; w < 8; w++) mm = fmaxf(mm, wred[w]);
            atomicMax(&g_maxkey, fkey(mm));
        }
    }
}

// ---------------------------------------------------------------------------
// kp exponentiation (in place) + per-chunk S_c = kp^T v, z_c = sum kp
__global__ void __launch_bounds__(256) k_chunk(const float* __restrict__ v) {
    extern __shared__ float sm[];
    float* sk = sm;             // [64][256] kp
    float* sv = sm + C_ * R_;   // [64][64]  v
    const int tile = blockIdx.x, tid = threadIdx.x;
    const float gstab = fdec(g_maxkey);
    float* kg = g_kf + (size_t)tile * (C_ * R_);

#pragma unroll
    for (int i = 0; i < 16; i++) {
        int i4 = tid + i * 256;
        float4 a = reinterpret_cast<float4*>(kg)[i4];
        a.x = RATIO_F * (fexp(a.x - gstab) + KEPS_F);
        a.y = RATIO_F * (fexp(a.y - gstab) + KEPS_F);
        a.z = RATIO_F * (fexp(a.z - gstab) + KEPS_F);
        a.w = RATIO_F * (fexp(a.w - gstab) + KEPS_F);
        reinterpret_cast<float4*>(sk)[i4] = a;
        reinterpret_cast<float4*>(kg)[i4] = a;
    }
    const float* vg = v + (size_t)tile * (C_ * D_);
#pragma unroll
    for (int i = 0; i < 4; i++) {
        int i4 = tid + i * 256;
        reinterpret_cast<float4*>(sv)[i4] =
            reinterpret_cast<const float4*>(vg)[i4];
    }
    __syncthreads();

    const int ri = tid >> 4, ei = tid & 15;
    float acc[16][4];
#pragma unroll
    for (int rr = 0; rr < 16; rr++)
#pragma unroll
        for (int c = 0; c < 4; c++) acc[rr][c] = 0.f;

#pragma unroll 4
    for (int t = 0; t < 64; t++) {
        float kkv[16];
#pragma unroll
        for (int jj = 0; jj < 4; jj++) {
            float4 k4 = *reinterpret_cast<const float4*>(sk + t * R_ + jj * 64 + ri * 4);
            kkv[4 * jj + 0] = k4.x; kkv[4 * jj + 1] = k4.y;
            kkv[4 * jj + 2] = k4.z; kkv[4 * jj + 3] = k4.w;
        }
        float4 vv = *reinterpret_cast<const float4*>(sv + t * D_ + ei * 4);
#pragma unroll
        for (int rr = 0; rr < 16; rr++) {
            acc[rr][0] = fmaf(kkv[rr], vv.x, acc[rr][0]);
            acc[rr][1] = fmaf(kkv[rr], vv.y, acc[rr][1]);
            acc[rr][2] = fmaf(kkv[rr], vv.z, acc[rr][2]);
            acc[rr][3] = fmaf(kkv[rr], vv.w, acc[rr][3]);
        }
    }
    float zs = 0.f;
#pragma unroll 8
    for (int t = 0; t < 64; t++) zs += sk[t * R_ + tid];

    float* So = g_sums + (size_t)tile * SSTRIDE;
#pragma unroll
    for (int jj = 0; jj < 4; jj++)
#pragma unroll
        for (int c = 0; c < 4; c++) {
            int r = jj * 64 + ri * 4 + c;
            float4 o = make_float4(acc[jj * 4 + c][0], acc[jj * 4 + c][1],
                                   acc[jj * 4 + c][2], acc[jj * 4 + c][3]);
            *reinterpret_cast<float4*>(So + r * D_ + ei * 4) = o;
        }
    So[R_ * D_ + tid] = zs;
}

// ---------------------------------------------------------------------------
// In-place exclusive prefix over 64 chunks per head. 16 heads x 13 col groups.
__global__ void __launch_bounds__(256) k_scan() {
    const int head = blockIdx.x / 13, grp = blockIdx.x % 13;
    const int c0 = grp * 1280 + threadIdx.x;
    float run[5] = {0.f, 0.f, 0.f, 0.f, 0.f};
    for (int c = 0; c < 64; c++) {
        size_t base = ((size_t)head * 64 + c) * SSTRIDE;
#pragma unroll
        for (int j = 0; j < 5; j++) {
            size_t a = base + c0 + j * 256;
            float t = g_sums[a];
            g_sums[a] = run[j];
            run[j] += t;
        }
    }
}

// ---------------------------------------------------------------------------
// Output: out = (Q@S_pre + mask(Q K^T) @ V) * Dinv, one block per chunk.
__global__ void __launch_bounds__(256) k_out(const float* __restrict__ v,
                                             float* __restrict__ out) {
    extern __shared__ float sm[];
    float* qT  = sm;            // [256][68] qp transposed
    float* kT  = qT + 17408;    // [256][68] kp transposed; later S [256*64]
    float* sv  = kT + 17408;    // [64][64]
    float* AT  = sv + 4096;     // [64][68] masked A transposed
    float* sz  = AT + 4352;     // [256] z_pre + eps
    float* sD  = sz + 256;      // [64] intra denom
    float* sDi = sD + 64;       // [64] 1/D

    const int tile = blockIdx.x, tid = threadIdx.x;
    const size_t fb = (size_t)tile * (C_ * R_);
    const float* qg = g_qp + fb;
    const float* kg = g_kf + fb;
    const float* Sg = g_sums + (size_t)tile * SSTRIDE;

#pragma unroll 8
    for (int i = 0; i < 64; i++) {
        int idx = tid + i * 256;
        int t = idx >> 8, r = idx & 255;
        qT[r * 68 + t] = qg[idx];
        kT[r * 68 + t] = kg[idx];
    }
#pragma unroll
    for (int i = 0; i < 4; i++) {
        int i4 = tid + i * 256;
        reinterpret_cast<float4*>(sv)[i4] =
            reinterpret_cast<const float4*>(v + (size_t)tile * (C_ * D_))[i4];
    }
    sz[tid] = Sg[R_ * D_ + tid] + AEPS_F;
    __syncthreads();

    {   // Phase A: A = Q K^T (K over r), mask, row sums, store transposed
        const int tg = tid >> 4, mg = tid & 15;
        float accA[4][4];
#pragma unroll
        for (int i = 0; i < 4; i++)
#pragma unroll
            for (int j = 0; j < 4; j++) accA[i][j] = 0.f;
#pragma unroll 4
        for (int r = 0; r < 256; r++) {
            float4 a = *reinterpret_cast<const float4*>(qT + r * 68 + tg * 4);
            float4 b = *reinterpret_cast<const float4*>(kT + r * 68 + mg * 4);
            float av[4] = {a.x, a.y, a.z, a.w};
            float bv[4] = {b.x, b.y, b.z, b.w};
#pragma unroll
            for (int i = 0; i < 4; i++)
#pragma unroll
                for (int j = 0; j < 4; j++)
                    accA[i][j] = fmaf(av[i], bv[j], accA[i][j]);
        }
#pragma unroll
        for (int i = 0; i < 4; i++) {
            int t = tg * 4 + i;
            float p = 0.f;
#pragma unroll
            for (int j = 0; j < 4; j++) {
                if (mg * 4 + j > t) accA[i][j] = 0.f;
                p += accA[i][j];
            }
#pragma unroll
            for (int off = 1; off < 16; off <<= 1)
                p += __shfl_xor_sync(0xffffffffu, p, off, 16);
            if (mg == 0) sD[t] = p;
        }
#pragma unroll
        for (int j = 0; j < 4; j++) {
            int m = mg * 4 + j;
            *reinterpret_cast<float4*>(AT + m * 68 + tg * 4) =
                make_float4(accA[0][j], accA[1][j], accA[2][j], accA[3][j]);
        }
    }
    __syncthreads();

    // load S_pre into kT region (flat [256][64]); compute Dinv
#pragma unroll
    for (int i = 0; i < 16; i++) {
        int i4 = tid + i * 256;
        reinterpret_cast<float4*>(kT)[i4] =
            reinterpret_cast<const float4*>(Sg)[i4];
    }
    if (tid < 64) {
        float s = 0.f;
#pragma unroll 8
        for (int r = 0; r < 256; r++) s = fmaf(qT[r * 68 + tid], sz[r], s);
        sDi[tid] = 1.0f / (s + sD[tid]);
    }
    __syncthreads();

    {   // Final: out = Q@S + A^T-as-stored @ V, scaled by Dinv
        const int tg = tid >> 4, eg = tid & 15;
        float acc[4][4];
#pragma unroll
        for (int i = 0; i < 4; i++)
#pragma unroll
            for (int j = 0; j < 4; j++) acc[i][j] = 0.f;
#pragma unroll 4
        for (int r = 0; r < 256; r++) {
            float4 a = *reinterpret_cast<const float4*>(qT + r * 68 + tg * 4);
            float4 b = *reinterpret_cast<const float4*>(kT + r * 64 + eg * 4);
            float av[4] = {a.x, a.y, a.z, a.w};
            float bv[4] = {b.x, b.y, b.z, b.w};
#pragma unroll
            for (int i = 0; i < 4; i++)
#pragma unroll
                for (int j = 0; j < 4; j++)
                    acc[i][j] = fmaf(av[i], bv[j], acc[i][j]);
        }
#pragma unroll 2
        for (int m = 0; m < 64; m++) {
            float4 a = *reinterpret_cast<const float4*>(AT + m * 68 + tg * 4);
            float4 b = *reinterpret_cast<const float4*>(sv + m * 64 + eg * 4);
            float av[4] = {a.x, a.y, a.z, a.w};
            float bv[4] = {b.x, b.y, b.z, b.w};
#pragma unroll
            for (int i = 0; i < 4; i++)
#pragma unroll
                for (int j = 0; j < 4; j++)
                    acc[i][j] = fmaf(av[i], bv[j], acc[i][j]);
        }
        float* og = out + (size_t)tile * (C_ * D_);
#pragma unroll
        for (int i = 0; i < 4; i++) {
            float di = sDi[tg * 4 + i];
            float4 o = make_float4(acc[i][0] * di, acc[i][1] * di,
                                   acc[i][2] * di, acc[i][3] * di);
            *reinterpret_cast<float4*>(og + (tg * 4 + i) * D_ + eg * 4) = o;
        }
    }
}

// ---------------------------------------------------------------------------
extern "C" void kernel_launch(void* const* d_in, const int* in_sizes, int n_in,
                              void* d_out, int out_size) {
    const float* q    = (const float*)d_in[0];
    const float* k    = (const float*)d_in[1];
    const float* v    = (const float*)d_in[2];
    const float* proj = (const float*)d_in[3];
    float* out = (float*)d_out;

    const int SMEM1 = (D_ * R_ + 64 * 65 + 64 + 8) * 4;   // 82464
    const int SMEM3 = (C_ * R_ + C_ * D_) * 4;            // 81920
    const int SMEM5 = (17408 * 2 + 4096 + 4352 + 256 + 64 + 64) * 4; // 174592

    cudaFuncSetAttribute(k_feat<true>,  cudaFuncAttributeMaxDynamicSharedMemorySize, SMEM1);
    cudaFuncSetAttribute(k_feat<false>, cudaFuncAttributeMaxDynamicSharedMemorySize, SMEM1);
    cudaFuncSetAttribute(k_chunk,       cudaFuncAttributeMaxDynamicSharedMemorySize, SMEM3);
    cudaFuncSetAttribute(k_out,         cudaFuncAttributeMaxDynamicSharedMemorySize, SMEM5);

    k_prep<<<1, 256>>>(proj);
    k_feat<true><<<NTILES, 256, SMEM1>>>(q);
    k_feat<false><<<NTILES, 256, SMEM1>>>(k);
    k_chunk<<<NTILES, 256, SMEM3>>>(v);
    k_scan<<<208, 256>>>();
    k_out<<<NTILES, 256, SMEM5>>>(v, out);
}

// round 2
// speedup vs baseline: 1.1017x; 1.1017x over previous
#include <cuda_runtime.h>
#include <cstdint>

// ---------------------------------------------------------------------------
// Performer causal linear attention, fp32.
// b=2 h=8 n=4096 d=64 r=256 chunk=64  -> 65536 tokens, 1024 chunks ("tiles")
//
//   k_prep   : projT[k][r] = proj[r][k]*d^-0.25 ; reset global max key
//   k_feat<Q>: qp = ratio*(exp(dash - diag - rowmax)+1e-4)        -> g_qp
//   k_feat<K>: store adj = dash - diag; atomicMax global max(dash) -> g_kf
//   k_chunk  : kp = exp-on-the-fly (smem only); per-chunk
//              S_c = kp^T v  [256x64], z_c = sum kp [256]          -> g_sums
//   k_scan   : exclusive prefix over 64 chunks per head (in place, prefetched)
//   k_out    : out = (Q@S_pre + causalmask(Q K^T) @ V) * Dinv (kp re-exp'd)
// ---------------------------------------------------------------------------

constexpr int D_ = 64;
constexpr int R_ = 256;
constexpr int C_ = 64;
constexpr int NTILES = 1024;
constexpr int SSTRIDE = R_ * D_ + R_;        // 16640 floats per chunk record

__device__ __align__(16) float g_projT[D_ * R_];
__device__ __align__(16) float g_qp[(size_t)NTILES * C_ * R_];
__device__ __align__(16) float g_kf[(size_t)NTILES * C_ * R_];
__device__ __align__(16) float g_sums[(size_t)NTILES * SSTRIDE];
__device__ unsigned g_maxkey;

#define NORM_F   0.35355339059327373f   /* 64^-0.25 */
#define DIAGC_F  0.0625f                /* 0.5 * 64^-0.5 */
#define RATIO_F  0.0625f                /* 256^-0.5 */
#define KEPS_F   1e-4f
#define AEPS_F   1e-6f

// fast e^x via exp2 polynomial (FFMA pipe only)
__device__ __forceinline__ float fexp(float x) {
    x = fmaxf(x, -87.0f);
    float t  = x * 1.4426950408889634f;
    float nf = rintf(t);
    float f  = t - nf;
    float p  = 1.5403530393e-4f;
    p = fmaf(p, f, 1.3333558146e-3f);
    p = fmaf(p, f, 9.6181291076e-3f);
    p = fmaf(p, f, 5.5504108665e-2f);
    p = fmaf(p, f, 2.4022650696e-1f);
    p = fmaf(p, f, 6.9314718056e-1f);
    p = fmaf(p, f, 1.0f);
    int n = (int)nf;
    return p * __int_as_float((n + 127) << 23);
}

__device__ __forceinline__ unsigned fkey(float f) {
    unsigned u = __float_as_uint(f);
    return (u & 0x80000000u) ? ~u : (u | 0x80000000u);
}
__device__ __forceinline__ float fdec(unsigned k) {
    return (k & 0x80000000u) ? __uint_as_float(k ^ 0x80000000u)
                             : __uint_as_float(~k);
}

// ---------------------------------------------------------------------------
__global__ void k_prep(const float* __restrict__ proj) {
    int tid = threadIdx.x;
    for (int idx = tid; idx < D_ * R_; idx += blockDim.x) {
        int kk = idx / R_, rr = idx % R_;
        g_projT[idx] = proj[rr * D_ + kk] * NORM_F;
    }
    if (tid == 0) g_maxkey = 0u;
}

// ---------------------------------------------------------------------------
// Feature map, 8x8 register tiles. Thread (tr,tc): rows t0=tr*8..+8,
// cols r in {tc*4..+4} u {128+tc*4..+4}.
template <bool ISQ>
__global__ void __launch_bounds__(256) k_feat(const float* __restrict__ x) {
    extern __shared__ float sm[];
    float* pT   = sm;                 // [64][256]
    float* xT   = sm + 16384;         // [64][68]  xT[k][t]
    float* dg   = xT + 64 * 68;       // [64]
    float* wred = dg + 64;            // [8]
    const int tile = blockIdx.x, tid = threadIdx.x;
    const float* xg = x + (size_t)tile * (C_ * D_);
    float* dst = (ISQ ? g_qp : g_kf) + (size_t)tile * (C_ * R_);

#pragma unroll
    for (int i = 0; i < 16; i++) {
        int i4 = tid + i * 256;
        reinterpret_cast<float4*>(pT)[i4] =
            reinterpret_cast<const float4*>(g_projT)[i4];
    }
#pragma unroll
    for (int i = 0; i < 4; i++) {
        int i4 = tid + i * 256;                 // float4 idx over 1024
        float4 vv = reinterpret_cast<const float4*>(xg)[i4];
        int t = (4 * i4) >> 6, kk = (4 * i4) & 63;
        xT[(kk + 0) * 68 + t] = vv.x;
        xT[(kk + 1) * 68 + t] = vv.y;
        xT[(kk + 2) * 68 + t] = vv.z;
        xT[(kk + 3) * 68 + t] = vv.w;
    }
    __syncthreads();
    if (tid < 64) {
        float s = 0.f;
#pragma unroll
        for (int kk = 0; kk < 64; kk++) {
            float vv = xT[kk * 68 + tid];
            s = fmaf(vv, vv, s);
        }
        dg[tid] = DIAGC_F * s;
    }
    __syncthreads();

    const int tr = tid >> 5, tc = tid & 31;
    const int t0 = tr * 8, r0 = tc * 4;
    float acc[8][8];
#pragma unroll
    for (int i = 0; i < 8; i++)
#pragma unroll
        for (int j = 0; j < 8; j++) acc[i][j] = 0.f;

#pragma unroll 4
    for (int kk = 0; kk < 64; kk++) {
        float4 a0 = *reinterpret_cast<const float4*>(xT + kk * 68 + t0);
        float4 a1 = *reinterpret_cast<const float4*>(xT + kk * 68 + t0 + 4);
        float4 b0 = *reinterpret_cast<const float4*>(pT + kk * 256 + r0);
        float4 b1 = *reinterpret_cast<const float4*>(pT + kk * 256 + 128 + r0);
        float av[8] = {a0.x, a0.y, a0.z, a0.w, a1.x, a1.y, a1.z, a1.w};
        float bv[8] = {b0.x, b0.y, b0.z, b0.w, b1.x, b1.y, b1.z, b1.w};
#pragma unroll
        for (int i = 0; i < 8; i++)
#pragma unroll
            for (int j = 0; j < 8; j++)
                acc[i][j] = fmaf(av[i], bv[j], acc[i][j]);
    }

    if (ISQ) {
#pragma unroll
        for (int i = 0; i < 8; i++) {
            int t = t0 + i;
            float m = acc[i][0];
#pragma unroll
            for (int j = 1; j < 8; j++) m = fmaxf(m, acc[i][j]);
#pragma unroll
            for (int off = 16; off >= 1; off >>= 1)
                m = fmaxf(m, __shfl_xor_sync(0xffffffffu, m, off));
            const float dgi = dg[t] + m;
            float4 o0, o1;
            o0.x = RATIO_F * (fexp(acc[i][0] - dgi) + KEPS_F);
            o0.y = RATIO_F * (fexp(acc[i][1] - dgi) + KEPS_F);
            o0.z = RATIO_F * (fexp(acc[i][2] - dgi) + KEPS_F);
            o0.w = RATIO_F * (fexp(acc[i][3] - dgi) + KEPS_F);
            o1.x = RATIO_F * (fexp(acc[i][4] - dgi) + KEPS_F);
            o1.y = RATIO_F * (fexp(acc[i][5] - dgi) + KEPS_F);
            o1.z = RATIO_F * (fexp(acc[i][6] - dgi) + KEPS_F);
            o1.w = RATIO_F * (fexp(acc[i][7] - dgi) + KEPS_F);
            *reinterpret_cast<float4*>(dst + t * 256 + r0) = o0;
            *reinterpret_cast<float4*>(dst + t * 256 + 128 + r0) = o1;
        }
    } else {
        float bm = -3.0e38f;
#pragma unroll
        for (int i = 0; i < 8; i++) {
            int t = t0 + i;
            const float dgi = dg[t];
            float4 o0, o1;
            o0.x = acc[i][0] - dgi; o0.y = acc[i][1] - dgi;
            o0.z = acc[i][2] - dgi; o0.w = acc[i][3] - dgi;
            o1.x = acc[i][4] - dgi; o1.y = acc[i][5] - dgi;
            o1.z = acc[i][6] - dgi; o1.w = acc[i][7] - dgi;
#pragma unroll
            for (int j = 0; j < 8; j++) bm = fmaxf(bm, acc[i][j]);
            *reinterpret_cast<float4*>(dst + t * 256 + r0) = o0;
            *reinterpret_cast<float4*>(dst + t * 256 + 128 + r0) = o1;
        }
#pragma unroll
        for (int off = 16; off >= 1; off >>= 1)
            bm = fmaxf(bm, __shfl_xor_sync(0xffffffffu, bm, off));
        if ((tid & 31) == 0) wred[tid >> 5] = bm;
        __syncthreads();
        if (tid == 0) {
            float mm = wred[0];
#pragma unroll
            for (int w = 1; w < 8; w++) mm = fmaxf(mm, wred[w]);
            atomicMax(&g_maxkey, fkey(mm));
        }
    }
}

// ---------------------------------------------------------------------------
// kp = exp(adj - stab) on the fly; S_c = kp^T v, z_c = sum kp. 8x8 tiles.
__global__ void __launch_bounds__(256) k_chunk(const float* __restrict__ v) {
    extern __shared__ float sm[];
    float* sk = sm;             // [64][256]
    float* sv = sm + 16384;     // [64][64]
    const int tile = blockIdx.x, tid = threadIdx.x;
    const float gstab = fdec(g_maxkey);
    const float* kg = g_kf + (size_t)tile * (C_ * R_);

#pragma unroll
    for (int i = 0; i < 16; i++) {
        int i4 = tid + i * 256;
        float4 a = reinterpret_cast<const float4*>(kg)[i4];
        a.x = RATIO_F * (fexp(a.x - gstab) + KEPS_F);
        a.y = RATIO_F * (fexp(a.y - gstab) + KEPS_F);
        a.z = RATIO_F * (fexp(a.z - gstab) + KEPS_F);
        a.w = RATIO_F * (fexp(a.w - gstab) + KEPS_F);
        reinterpret_cast<float4*>(sk)[i4] = a;
    }
    const float* vg = v + (size_t)tile * (C_ * D_);
#pragma unroll
    for (int i = 0; i < 4; i++) {
        int i4 = tid + i * 256;
        reinterpret_cast<float4*>(sv)[i4] =
            reinterpret_cast<const float4*>(vg)[i4];
    }
    __syncthreads();

    const int ri = tid >> 3, ei = tid & 7;
    const int r0 = ri * 8, e0 = ei * 8;
    float acc[8][8];
#pragma unroll
    for (int i = 0; i < 8; i++)
#pragma unroll
        for (int j = 0; j < 8; j++) acc[i][j] = 0.f;

#pragma unroll 4
    for (int t = 0; t < 64; t++) {
        float4 a0 = *reinterpret_cast<const float4*>(sk + t * 256 + r0);
        float4 a1 = *reinterpret_cast<const float4*>(sk + t * 256 + r0 + 4);
        float4 b0 = *reinterpret_cast<const float4*>(sv + t * 64 + e0);
        float4 b1 = *reinterpret_cast<const float4*>(sv + t * 64 + e0 + 4);
        float av[8] = {a0.x, a0.y, a0.z, a0.w, a1.x, a1.y, a1.z, a1.w};
        float bv[8] = {b0.x, b0.y, b0.z, b0.w, b1.x, b1.y, b1.z, b1.w};
#pragma unroll
        for (int i = 0; i < 8; i++)
#pragma unroll
            for (int j = 0; j < 8; j++)
                acc[i][j] = fmaf(av[i], bv[j], acc[i][j]);
    }
    float zs = 0.f;
#pragma unroll 8
    for (int t = 0; t < 64; t++) zs += sk[t * 256 + tid];

    float* So = g_sums + (size_t)tile * SSTRIDE;
#pragma unroll
    for (int rr = 0; rr < 8; rr++) {
        int r = r0 + rr;
        *reinterpret_cast<float4*>(So + r * 64 + e0) =
            make_float4(acc[rr][0], acc[rr][1], acc[rr][2], acc[rr][3]);
        *reinterpret_cast<float4*>(So + r * 64 + e0 + 4) =
            make_float4(acc[rr][4], acc[rr][5], acc[rr][6], acc[rr][7]);
    }
    So[R_ * D_ + tid] = zs;
}

// ---------------------------------------------------------------------------
// Exclusive prefix over 64 chunks per head; one column per thread, prefetched.
__global__ void __launch_bounds__(256) k_scan() {
    const int head = blockIdx.x / 65, grp = blockIdx.x % 65;
    size_t base = (size_t)head * 64 * SSTRIDE + grp * 256 + threadIdx.x;
    float run = 0.f;
    float nxt = g_sums[base];
#pragma unroll 1
    for (int c = 0; c < 64; c++) {
        float cur = nxt;
        if (c < 63) nxt = g_sums[base + (size_t)(c + 1) * SSTRIDE];
        g_sums[base + (size_t)c * SSTRIDE] = run;
        run += cur;
    }
}

// ---------------------------------------------------------------------------
// out = (Q@S_pre + mask(Q K^T) @ V) * Dinv. XOR-swizzled smem, no transposes.
// element (t,r) of q_s/k_s stored at t*256 + (((r>>2)^(t&15))<<2) + (r&3).
// element (t,m) of A_s stored at t*64 + (((m>>2)^(t&15))<<2) + (m&3).
__global__ void __launch_bounds__(256) k_out(const float* __restrict__ v,
                                             float* __restrict__ out) {
    extern __shared__ float sm[];
    float* q_s = sm;            // 16384 swizzled
    float* k_s = q_s + 16384;   // 16384 swizzled; later S natural [256][64]
    float* v_s = k_s + 16384;   // 4096 natural
    float* A_s = v_s + 4096;    // 4096 swizzled
    float* sz  = A_s + 4096;    // 256
    float* sD  = sz + 256;      // 64
    float* sDi = sD + 64;       // 64

    const int tile = blockIdx.x, tid = threadIdx.x;
    const float* qg = g_qp + (size_t)tile * (C_ * R_);
    const float* kg = g_kf + (size_t)tile * (C_ * R_);
    const float* Sg = g_sums + (size_t)tile * SSTRIDE;
    const float gstab = fdec(g_maxkey);

#pragma unroll
    for (int i = 0; i < 16; i++) {
        int i4 = tid + i * 256;             // float4 idx over 4096
        int t = i4 >> 6, r4 = i4 & 63;
        int u = r4 ^ (t & 15);
        float4 a = reinterpret_cast<const float4*>(qg)[i4];
        *reinterpret_cast<float4*>(q_s + t * 256 + u * 4) = a;
        float4 b = reinterpret_cast<const float4*>(kg)[i4];
        b.x = RATIO_F * (fexp(b.x - gstab) + KEPS_F);
        b.y = RATIO_F * (fexp(b.y - gstab) + KEPS_F);
        b.z = RATIO_F * (fexp(b.z - gstab) + KEPS_F);
        b.w = RATIO_F * (fexp(b.w - gstab) + KEPS_F);
        *reinterpret_cast<float4*>(k_s + t * 256 + u * 4) = b;
    }
#pragma unroll
    for (int i = 0; i < 4; i++) {
        int i4 = tid + i * 256;
        reinterpret_cast<float4*>(v_s)[i4] =
            reinterpret_cast<const float4*>(v + (size_t)tile * (C_ * D_))[i4];
    }
    sz[tid] = Sg[R_ * D_ + tid] + AEPS_F;
    __syncthreads();

    const int tg = tid >> 4;    // 0..15 : t = tg + 16*i
    const int mg = tid & 15;    // 0..15 : m = mg + 16*j ; e0 = mg*4
    const int e0 = mg * 4;

    {   // Phase A: A = qp kp^T over r, mask m<=t, row sums
        float accA[4][4];
#pragma unroll
        for (int i = 0; i < 4; i++)
#pragma unroll
            for (int j = 0; j < 4; j++) accA[i][j] = 0.f;
#pragma unroll 2
        for (int rr = 0; rr < 64; rr++) {
            float4 a[4], b[4];
#pragma unroll
            for (int i = 0; i < 4; i++)
                a[i] = *reinterpret_cast<const float4*>(
                    q_s + (tg + 16 * i) * 256 + ((rr ^ tg) << 2));
#pragma unroll
            for (int j = 0; j < 4; j++)
                b[j] = *reinterpret_cast<const float4*>(
                    k_s + (mg + 16 * j) * 256 + ((rr ^ mg) << 2));
#pragma unroll
            for (int i = 0; i < 4; i++)
#pragma unroll
                for (int j = 0; j < 4; j++) {
                    accA[i][j] = fmaf(a[i].x, b[j].x, accA[i][j]);
                    accA[i][j] = fmaf(a[i].y, b[j].y, accA[i][j]);
                    accA[i][j] = fmaf(a[i].z, b[j].z, accA[i][j]);
                    accA[i][j] = fmaf(a[i].w, b[j].w, accA[i][j]);
                }
        }
#pragma unroll
        for (int i = 0; i < 4; i++) {
            int t = tg + 16 * i;
            float p = 0.f;
#pragma unroll
            for (int j = 0; j < 4; j++) {
                int m = mg + 16 * j;
                if (m > t) accA[i][j] = 0.f;
                p += accA[i][j];
            }
#pragma unroll
            for (int off = 1; off < 16; off <<= 1)
                p += __shfl_xor_sync(0xffffffffu, p, off, 16);
            if (mg == 0) sD[t] = p;
#pragma unroll
            for (int j = 0; j < 4; j++) {
                int m = mg + 16 * j;
                A_s[t * 64 + ((((m >> 2) ^ (t & 15))) << 2) + (m & 3)] = accA[i][j];
            }
        }
    }
    __syncthreads();

    // overwrite k_s with S_pre (natural [256][64]); compute Dinv
#pragma unroll
    for (int i = 0; i < 16; i++) {
        int i4 = tid + i * 256;
        reinterpret_cast<float4*>(k_s)[i4] =
            reinterpret_cast<const float4*>(Sg)[i4];
    }
    if (tid < 64) {
        float s = 0.f;
        const int key = tid & 15;
#pragma unroll 8
        for (int r = 0; r < 256; r++)
            s = fmaf(q_s[tid * 256 + (((r >> 2) ^ key) << 2) + (r & 3)],
                     sz[r], s);
        sDi[tid] = 1.0f / (s + sD[tid]);
    }
    __syncthreads();

    {   // Phase B: out = Q@S + A@V, scaled by Dinv
        float acc[4][4];
#pragma unroll
        for (int i = 0; i < 4; i++)
#pragma unroll
            for (int j = 0; j < 4; j++) acc[i][j] = 0.f;
#pragma unroll 2
        for (int rr = 0; rr < 64; rr++) {
            float4 a[4], b[4];
#pragma unroll
            for (int i = 0; i < 4; i++)
                a[i] = *reinterpret_cast<const float4*>(
                    q_s + (tg + 16 * i) * 256 + ((rr ^ tg) << 2));
#pragma unroll
            for (int c = 0; c < 4; c++)
                b[c] = *reinterpret_cast<const float4*>(
                    k_s + (rr * 4 + c) * 64 + e0);
#pragma unroll
            for (int i = 0; i < 4; i++) {
                acc[i][0] = fmaf(a[i].x, b[0].x, acc[i][0]);
                acc[i][1] = fmaf(a[i].x, b[0].y, acc[i][1]);
                acc[i][2] = fmaf(a[i].x, b[0].z, acc[i][2]);
                acc[i][3] = fmaf(a[i].x, b[0].w, acc[i][3]);
                acc[i][0] = fmaf(a[i].y, b[1].x, acc[i][0]);
                acc[i][1] = fmaf(a[i].y, b[1].y, acc[i][1]);
                acc[i][2] = fmaf(a[i].y, b[1].z, acc[i][2]);
                acc[i][3] = fmaf(a[i].y, b[1].w, acc[i][3]);
                acc[i][0] = fmaf(a[i].z, b[2].x, acc[i][0]);
                acc[i][1] = fmaf(a[i].z, b[2].y, acc[i][1]);
                acc[i][2] = fmaf(a[i].z, b[2].z, acc[i][2]);
                acc[i][3] = fmaf(a[i].z, b[2].w, acc[i][3]);
                acc[i][0] = fmaf(a[i].w, b[3].x, acc[i][0]);
                acc[i][1] = fmaf(a[i].w, b[3].y, acc[i][1]);
                acc[i][2] = fmaf(a[i].w, b[3].z, acc[i][2]);
                acc[i][3] = fmaf(a[i].w, b[3].w, acc[i][3]);
            }
        }
#pragma unroll
        for (int mm = 0; mm < 16; mm++) {
            float4 a[4], b[4];
#pragma unroll
            for (int i = 0; i < 4; i++) {
                int t = tg + 16 * i;
                a[i] = *reinterpret_cast<const float4*>(
                    A_s + t * 64 + ((mm ^ tg) << 2));
            }
#pragma unroll
            for (int c = 0; c < 4; c++)
                b[c] = *reinterpret_cast<const float4*>(
                    v_s + (mm * 4 + c) * 64 + e0);
#pragma unroll
            for (int i = 0; i < 4; i++) {
                acc[i][0] = fmaf(a[i].x, b[0].x, acc[i][0]);
                acc[i][1] = fmaf(a[i].x, b[0].y, acc[i][1]);
                acc[i][2] = fmaf(a[i].x, b[0].z, acc[i][2]);
                acc[i][3] = fmaf(a[i].x, b[0].w, acc[i][3]);
                acc[i][0] = fmaf(a[i].y, b[1].x, acc[i][0]);
                acc[i][1] = fmaf(a[i].y, b[1].y, acc[i][1]);
                acc[i][2] = fmaf(a[i].y, b[1].z, acc[i][2]);
                acc[i][3] = fmaf(a[i].y, b[1].w, acc[i][3]);
                acc[i][0] = fmaf(a[i].z, b[2].x, acc[i][0]);
                acc[i][1] = fmaf(a[i].z, b[2].y, acc[i][1]);
                acc[i][2] = fmaf(a[i].z, b[2].z, acc[i][2]);
                acc[i][3] = fmaf(a[i].z, b[2].w, acc[i][3]);
                acc[i][0] = fmaf(a[i].w, b[3].x, acc[i][0]);
                acc[i][1] = fmaf(a[i].w, b[3].y, acc[i][1]);
                acc[i][2] = fmaf(a[i].w, b[3].z, acc[i][2]);
                acc[i][3] = fmaf(a[i].w, b[3].w, acc[i][3]);
            }
        }
        float* og = out + (size_t)tile * (C_ * D_);
#pragma unroll
        for (int i = 0; i < 4; i++) {
            int t = tg + 16 * i;
            float di = sDi[t];
            *reinterpret_cast<float4*>(og + t * 64 + e0) =
                make_float4(acc[i][0] * di, acc[i][1] * di,
                            acc[i][2] * di, acc[i][3] * di);
        }
    }
}

// ---------------------------------------------------------------------------
extern "C" void kernel_launch(void* const* d_in, const int* in_sizes, int n_in,
                              void* d_out, int out_size) {
    const float* q    = (const float*)d_in[0];
    const float* k    = (const float*)d_in[1];
    const float* v    = (const float*)d_in[2];
    const float* proj = (const float*)d_in[3];
    float* out = (float*)d_out;

    const int SMEM_F = (16384 + 64 * 68 + 64 + 8) * 4;            // ~83 KB
    const int SMEM_C = (16384 + 4096) * 4;                        // 80 KB
    const int SMEM_O = (16384 * 2 + 4096 + 4096 + 256 + 64 + 64) * 4; // ~165 KB

    cudaFuncSetAttribute(k_feat<true>,  cudaFuncAttributeMaxDynamicSharedMemorySize, SMEM_F);
    cudaFuncSetAttribute(k_feat<false>, cudaFuncAttributeMaxDynamicSharedMemorySize, SMEM_F);
    cudaFuncSetAttribute(k_chunk,       cudaFuncAttributeMaxDynamicSharedMemorySize, SMEM_C);
    cudaFuncSetAttribute(k_out,         cudaFuncAttributeMaxDynamicSharedMemorySize, SMEM_O);

    k_prep<<<1, 256>>>(proj);
    k_feat<true><<<NTILES, 256, SMEM_F>>>(q);
    k_feat<false><<<NTILES, 256, SMEM_F>>>(k);
    k_chunk<<<NTILES, 256, SMEM_C>>>(v);
    k_scan<<<1040, 256>>>();
    k_out<<<NTILES, 256, SMEM_O>>>(v, out);
}

// round 3
// speedup vs baseline: 1.1353x; 1.0305x over previous
#include <cuda_runtime.h>
#include <cstdint>

// ---------------------------------------------------------------------------
// Performer causal linear attention, fp32, FFMA2 (fma.rn.f32x2) GEMM cores.
// b=2 h=8 n=4096 d=64 r=256 chunk=64  -> 65536 tokens, 1024 chunks ("tiles")
// ---------------------------------------------------------------------------

constexpr int D_ = 64;
constexpr int R_ = 256;
constexpr int C_ = 64;
constexpr int NTILES = 1024;
constexpr int SSTRIDE = R_ * D_ + R_;        // 16640 floats per chunk record

__device__ __align__(16) float g_projT[D_ * R_];
__device__ __align__(16) float g_qp[(size_t)NTILES * C_ * R_];
__device__ __align__(16) float g_kf[(size_t)NTILES * C_ * R_];
__device__ __align__(16) float g_sums[(size_t)NTILES * SSTRIDE];
__device__ unsigned g_maxkey;

#define NORM_F   0.35355339059327373f   /* 64^-0.25 */
#define DIAGC_F  0.0625f                /* 0.5 * 64^-0.5 */
#define RATIO_F  0.0625f                /* 256^-0.5 */
#define KEPS_F   1e-4f
#define AEPS_F   1e-6f

typedef unsigned long long u64;

// packed fp32x2 helpers (sm_100+)
__device__ __forceinline__ u64 pk2(float x) {
    u64 r; asm("mov.b64 %0, {%1, %1};" : "=l"(r) : "f"(x)); return r;
}
__device__ __forceinline__ void fma2(u64& d, u64 a, u64 b) {
    asm("fma.rn.f32x2 %0, %1, %2, %0;" : "+l"(d) : "l"(a), "l"(b));
}
__device__ __forceinline__ float2 up2(u64 a) {
    float2 f; asm("mov.b64 {%0, %1}, %2;" : "=f"(f.x), "=f"(f.y) : "l"(a));
    return f;
}

// fast e^x via exp2 polynomial (FFMA pipe only)
__device__ __forceinline__ float fexp(float x) {
    x = fmaxf(x, -87.0f);
    float t  = x * 1.4426950408889634f;
    float nf = rintf(t);
    float f  = t - nf;
    float p  = 1.5403530393e-4f;
    p = fmaf(p, f, 1.3333558146e-3f);
    p = fmaf(p, f, 9.6181291076e-3f);
    p = fmaf(p, f, 5.5504108665e-2f);
    p = fmaf(p, f, 2.4022650696e-1f);
    p = fmaf(p, f, 6.9314718056e-1f);
    p = fmaf(p, f, 1.0f);
    int n = (int)nf;
    return p * __int_as_float((n + 127) << 23);
}

__device__ __forceinline__ unsigned fkey(float f) {
    unsigned u = __float_as_uint(f);
    return (u & 0x80000000u) ? ~u : (u | 0x80000000u);
}
__device__ __forceinline__ float fdec(unsigned k) {
    return (k & 0x80000000u) ? __uint_as_float(k ^ 0x80000000u)
                             : __uint_as_float(~k);
}

// ---------------------------------------------------------------------------
__global__ void k_prep(const float* __restrict__ proj) {
    int tid = threadIdx.x;
    for (int idx = tid; idx < D_ * R_; idx += blockDim.x) {
        int kk = idx / R_, rr = idx % R_;
        g_projT[idx] = proj[rr * D_ + kk] * NORM_F;
    }
    if (tid == 0) g_maxkey = 0u;
}

// ---------------------------------------------------------------------------
// Feature map, 8x8 register tiles, FFMA2 inner loop.
template <bool ISQ>
__global__ void __launch_bounds__(256) k_feat(const float* __restrict__ x) {
    extern __shared__ float sm[];
    float* pT   = sm;                 // [64][256]
    float* xT   = sm + 16384;         // [64][68]  xT[k][t]
    float* dg   = xT + 64 * 68;       // [64]
    float* wred = dg + 64;            // [8]
    const int tile = blockIdx.x, tid = threadIdx.x;
    const float* xg = x + (size_t)tile * (C_ * D_);
    float* dst = (ISQ ? g_qp : g_kf) + (size_t)tile * (C_ * R_);

#pragma unroll
    for (int i = 0; i < 16; i++) {
        int i4 = tid + i * 256;
        reinterpret_cast<float4*>(pT)[i4] =
            reinterpret_cast<const float4*>(g_projT)[i4];
    }
#pragma unroll
    for (int i = 0; i < 4; i++) {
        int i4 = tid + i * 256;
        float4 vv = reinterpret_cast<const float4*>(xg)[i4];
        int t = (4 * i4) >> 6, kk = (4 * i4) & 63;
        xT[(kk + 0) * 68 + t] = vv.x;
        xT[(kk + 1) * 68 + t] = vv.y;
        xT[(kk + 2) * 68 + t] = vv.z;
        xT[(kk + 3) * 68 + t] = vv.w;
    }
    __syncthreads();
    if (tid < 64) {
        float s = 0.f;
#pragma unroll
        for (int kk = 0; kk < 64; kk++) {
            float vv = xT[kk * 68 + tid];
            s = fmaf(vv, vv, s);
        }
        dg[tid] = DIAGC_F * s;
    }
    __syncthreads();

    const int tr = tid >> 5, tc = tid & 31;
    const int t0 = tr * 8, r0 = tc * 4;
    u64 acc[8][4];
#pragma unroll
    for (int i = 0; i < 8; i++)
#pragma unroll
        for (int j = 0; j < 4; j++) acc[i][j] = 0ull;

#pragma unroll 4
    for (int kk = 0; kk < 64; kk++) {
        float4 a0 = *reinterpret_cast<const float4*>(xT + kk * 68 + t0);
        float4 a1 = *reinterpret_cast<const float4*>(xT + kk * 68 + t0 + 4);
        ulonglong2 B0 = *reinterpret_cast<const ulonglong2*>(pT + kk * 256 + r0);
        ulonglong2 B1 = *reinterpret_cast<const ulonglong2*>(pT + kk * 256 + 128 + r0);
        u64 b[4] = {B0.x, B0.y, B1.x, B1.y};
        u64 ap[8] = {pk2(a0.x), pk2(a0.y), pk2(a0.z), pk2(a0.w),
                     pk2(a1.x), pk2(a1.y), pk2(a1.z), pk2(a1.w)};
#pragma unroll
        for (int i = 0; i < 8; i++)
#pragma unroll
            for (int j = 0; j < 4; j++) fma2(acc[i][j], ap[i], b[j]);
    }

#pragma unroll
    for (int i = 0; i < 8; i++) {
        float2 p0 = up2(acc[i][0]), p1 = up2(acc[i][1]);
        float2 p2 = up2(acc[i][2]), p3 = up2(acc[i][3]);
        float a8[8] = {p0.x, p0.y, p1.x, p1.y, p2.x, p2.y, p3.x, p3.y};
        int t = t0 + i;
        if (ISQ) {
            float m = a8[0];
#pragma unroll
            for (int j = 1; j < 8; j++) m = fmaxf(m, a8[j]);
#pragma unroll
            for (int off = 16; off >= 1; off >>= 1)
                m = fmaxf(m, __shfl_xor_sync(0xffffffffu, m, off));
            const float dgi = dg[t] + m;
            float4 o0, o1;
            o0.x = RATIO_F * (fexp(a8[0] - dgi) + KEPS_F);
            o0.y = RATIO_F * (fexp(a8[1] - dgi) + KEPS_F);
            o0.z = RATIO_F * (fexp(a8[2] - dgi) + KEPS_F);
            o0.w = RATIO_F * (fexp(a8[3] - dgi) + KEPS_F);
            o1.x = RATIO_F * (fexp(a8[4] - dgi) + KEPS_F);
            o1.y = RATIO_F * (fexp(a8[5] - dgi) + KEPS_F);
            o1.z = RATIO_F * (fexp(a8[6] - dgi) + KEPS_F);
            o1.w = RATIO_F * (fexp(a8[7] - dgi) + KEPS_F);
            *reinterpret_cast<float4*>(dst + t * 256 + r0) = o0;
            *reinterpret_cast<float4*>(dst + t * 256 + 128 + r0) = o1;
        } else {
            const float dgi = dg[t];
            float4 o0, o1;
            o0.x = a8[0] - dgi; o0.y = a8[1] - dgi;
            o0.z = a8[2] - dgi; o0.w = a8[3] - dgi;
            o1.x = a8[4] - dgi; o1.y = a8[5] - dgi;
            o1.z = a8[6] - dgi; o1.w = a8[7] - dgi;
            *reinterpret_cast<float4*>(dst + t * 256 + r0) = o0;
            *reinterpret_cast<float4*>(dst + t * 256 + 128 + r0) = o1;
            // fold into running block max via wred below
            float bm = fmaxf(fmaxf(fmaxf(o0.x, o0.y), fmaxf(o0.z, o0.w)),
                             fmaxf(fmaxf(o1.x, o1.y), fmaxf(o1.z, o1.w))) + dgi;
            if (i == 0) wred[0] = wred[0]; // no-op keep structure
            // accumulate per-thread max in a8[0] slot via register reuse:
            dg[t] = dgi;  // unchanged
            // handled after loop (see bmax below)
            a8[0] = bm;   // stash
            acc[i][0] = pk2(bm); // keep value alive for after-loop reduction
        }
    }
    if (!ISQ) {
        float bm = -3.0e38f;
#pragma unroll
        for (int i = 0; i < 8; i++) bm = fmaxf(bm, up2(acc[i][0]).x);
#pragma unroll
        for (int off = 16; off >= 1; off >>= 1)
            bm = fmaxf(bm, __shfl_xor_sync(0xffffffffu, bm, off));
        if ((tid & 31) == 0) wred[tid >> 5] = bm;
        __syncthreads();
        if (tid == 0) {
            float mm = wred[0];
#pragma unroll
            for (int w = 1; w < 8; w++) mm = fmaxf(mm, wred[w]);
            atomicMax(&g_maxkey, fkey(mm));
        }
    }
}

// ---------------------------------------------------------------------------
// kp = exp(adj - stab) on the fly; S_c = kp^T v, z_c = sum kp. FFMA2 core.
__global__ void __launch_bounds__(256) k_chunk(const float* __restrict__ v) {
    extern __shared__ float sm[];
    float* sk = sm;             // [64][256]
    float* sv = sm + 16384;     // [64][64]
    const int tile = blockIdx.x, tid = threadIdx.x;
    const float gstab = fdec(g_maxkey);
    const float* kg = g_kf + (size_t)tile * (C_ * R_);

#pragma unroll
    for (int i = 0; i < 16; i++) {
        int i4 = tid + i * 256;
        float4 a = reinterpret_cast<const float4*>(kg)[i4];
        a.x = RATIO_F * (fexp(a.x - gstab) + KEPS_F);
        a.y = RATIO_F * (fexp(a.y - gstab) + KEPS_F);
        a.z = RATIO_F * (fexp(a.z - gstab) + KEPS_F);
        a.w = RATIO_F * (fexp(a.w - gstab) + KEPS_F);
        reinterpret_cast<float4*>(sk)[i4] = a;
    }
    const float* vg = v + (size_t)tile * (C_ * D_);
#pragma unroll
    for (int i = 0; i < 4; i++) {
        int i4 = tid + i * 256;
        reinterpret_cast<float4*>(sv)[i4] =
            reinterpret_cast<const float4*>(vg)[i4];
    }
    __syncthreads();

    const int ri = tid >> 3, ei = tid & 7;
    const int r0 = ri * 8, e0 = ei * 8;
    u64 acc[8][4];
#pragma unroll
    for (int i = 0; i < 8; i++)
#pragma unroll
        for (int j = 0; j < 4; j++) acc[i][j] = 0ull;

#pragma unroll 4
    for (int t = 0; t < 64; t++) {
        float4 a0 = *reinterpret_cast<const float4*>(sk + t * 256 + r0);
        float4 a1 = *reinterpret_cast<const float4*>(sk + t * 256 + r0 + 4);
        ulonglong2 B0 = *reinterpret_cast<const ulonglong2*>(sv + t * 64 + e0);
        ulonglong2 B1 = *reinterpret_cast<const ulonglong2*>(sv + t * 64 + e0 + 4);
        u64 b[4] = {B0.x, B0.y, B1.x, B1.y};
        u64 ap[8] = {pk2(a0.x), pk2(a0.y), pk2(a0.z), pk2(a0.w),
                     pk2(a1.x), pk2(a1.y), pk2(a1.z), pk2(a1.w)};
#pragma unroll
        for (int i = 0; i < 8; i++)
#pragma unroll
            for (int j = 0; j < 4; j++) fma2(acc[i][j], ap[i], b[j]);
    }
    float zs = 0.f;
#pragma unroll 8
    for (int t = 0; t < 64; t++) zs += sk[t * 256 + tid];

    float* So = g_sums + (size_t)tile * SSTRIDE;
#pragma unroll
    for (int rr = 0; rr < 8; rr++) {
        int r = r0 + rr;
        float2 p0 = up2(acc[rr][0]), p1 = up2(acc[rr][1]);
        float2 p2 = up2(acc[rr][2]), p3 = up2(acc[rr][3]);
        *reinterpret_cast<float4*>(So + r * 64 + e0) =
            make_float4(p0.x, p0.y, p1.x, p1.y);
        *reinterpret_cast<float4*>(So + r * 64 + e0 + 4) =
            make_float4(p2.x, p2.y, p3.x, p3.y);
    }
    So[R_ * D_ + tid] = zs;
}

// ---------------------------------------------------------------------------
// Exclusive prefix over 64 chunks per head; one column per thread, prefetched.
__global__ void __launch_bounds__(256) k_scan() {
    const int head = blockIdx.x / 65, grp = blockIdx.x % 65;
    size_t base = (size_t)head * 64 * SSTRIDE + grp * 256 + threadIdx.x;
    float run = 0.f;
    float nxt = g_sums[base];
#pragma unroll 1
    for (int c = 0; c < 64; c++) {
        float cur = nxt;
        if (c < 63) nxt = g_sums[base + (size_t)(c + 1) * SSTRIDE];
        g_sums[base + (size_t)c * SSTRIDE] = run;
        run += cur;
    }
}

// ---------------------------------------------------------------------------
// out = (Q@S_pre + mask(Q K^T) @ V) * Dinv. XOR-swizzled smem, FFMA2 cores.
__global__ void __launch_bounds__(256) k_out(const float* __restrict__ v,
                                             float* __restrict__ out) {
    extern __shared__ float sm[];
    float* q_s = sm;            // 16384 swizzled
    float* k_s = q_s + 16384;   // 16384 swizzled; later S natural [256][64]
    float* v_s = k_s + 16384;   // 4096 natural
    float* A_s = v_s + 4096;    // 4096 swizzled
    float* sz  = A_s + 4096;    // 256
    float* sD  = sz + 256;      // 64
    float* sDi = sD + 64;       // 64

    const int tile = blockIdx.x, tid = threadIdx.x;
    const float* qg = g_qp + (size_t)tile * (C_ * R_);
    const float* kg = g_kf + (size_t)tile * (C_ * R_);
    const float* Sg = g_sums + (size_t)tile * SSTRIDE;
    const float gstab = fdec(g_maxkey);

#pragma unroll
    for (int i = 0; i < 16; i++) {
        int i4 = tid + i * 256;
        int t = i4 >> 6, r4 = i4 & 63;
        int u = r4 ^ (t & 15);
        float4 a = reinterpret_cast<const float4*>(qg)[i4];
        *reinterpret_cast<float4*>(q_s + t * 256 + u * 4) = a;
        float4 b = reinterpret_cast<const float4*>(kg)[i4];
        b.x = RATIO_F * (fexp(b.x - gstab) + KEPS_F);
        b.y = RATIO_F * (fexp(b.y - gstab) + KEPS_F);
        b.z = RATIO_F * (fexp(b.z - gstab) + KEPS_F);
        b.w = RATIO_F * (fexp(b.w - gstab) + KEPS_F);
        *reinterpret_cast<float4*>(k_s + t * 256 + u * 4) = b;
    }
#pragma unroll
    for (int i = 0; i < 4; i++) {
        int i4 = tid + i * 256;
        reinterpret_cast<float4*>(v_s)[i4] =
            reinterpret_cast<const float4*>(v + (size_t)tile * (C_ * D_))[i4];
    }
    sz[tid] = Sg[R_ * D_ + tid] + AEPS_F;
    __syncthreads();

    const int tg = tid >> 4;    // t = tg + 16*i
    const int mg = tid & 15;    // m = mg + 16*j ; e0 = mg*4
    const int e0 = mg * 4;

    {   // Phase A: A = qp kp^T over r (dot-packed: zero pack overhead)
        u64 accA[4][4];
#pragma unroll
        for (int i = 0; i < 4; i++)
#pragma unroll
            for (int j = 0; j < 4; j++) accA[i][j] = 0ull;
#pragma unroll 2
        for (int rr = 0; rr < 64; rr++) {
            ulonglong2 a[4], b[4];
#pragma unroll
            for (int i = 0; i < 4; i++)
                a[i] = *reinterpret_cast<const ulonglong2*>(
                    q_s + (tg + 16 * i) * 256 + ((rr ^ tg) << 2));
#pragma unroll
            for (int j = 0; j < 4; j++)
                b[j] = *reinterpret_cast<const ulonglong2*>(
                    k_s + (mg + 16 * j) * 256 + ((rr ^ mg) << 2));
#pragma unroll
            for (int i = 0; i < 4; i++)
#pragma unroll
                for (int j = 0; j < 4; j++) {
                    fma2(accA[i][j], a[i].x, b[j].x);
                    fma2(accA[i][j], a[i].y, b[j].y);
                }
        }
#pragma unroll
        for (int i = 0; i < 4; i++) {
            int t = tg + 16 * i;
            float p = 0.f;
            float af[4];
#pragma unroll
            for (int j = 0; j < 4; j++) {
                float2 h = up2(accA[i][j]);
                af[j] = h.x + h.y;
                int m = mg + 16 * j;
                if (m > t) af[j] = 0.f;
                p += af[j];
            }
#pragma unroll
            for (int off = 1; off < 16; off <<= 1)
                p += __shfl_xor_sync(0xffffffffu, p, off, 16);
            if (mg == 0) sD[t] = p;
#pragma unroll
            for (int j = 0; j < 4; j++) {
                int m = mg + 16 * j;
                A_s[t * 64 + ((((m >> 2) ^ (t & 15))) << 2) + (m & 3)] = af[j];
            }
        }
    }
    __syncthreads();

    // overwrite k_s with S_pre (natural [256][64]); compute Dinv
#pragma unroll
    for (int i = 0; i < 16; i++) {
        int i4 = tid + i * 256;
        reinterpret_cast<float4*>(k_s)[i4] =
            reinterpret_cast<const float4*>(Sg)[i4];
    }
    if (tid < 64) {
        float s = 0.f;
        const int key = tid & 15;
#pragma unroll 8
        for (int r = 0; r < 256; r++)
            s = fmaf(q_s[tid * 256 + (((r >> 2) ^ key) << 2) + (r & 3)],
                     sz[r], s);
        sDi[tid] = 1.0f / (s + sD[tid]);
    }
    __syncthreads();

    {   // Phase B: out = Q@S + A@V, FFMA2 outer-product
        u64 acc[4][2];
#pragma unroll
        for (int i = 0; i < 4; i++) { acc[i][0] = 0ull; acc[i][1] = 0ull; }
#pragma unroll 2
        for (int rr = 0; rr < 64; rr++) {
            float4 a[4];
            ulonglong2 b[4];
#pragma unroll
            for (int i = 0; i < 4; i++)
                a[i] = *reinterpret_cast<const float4*>(
                    q_s + (tg + 16 * i) * 256 + ((rr ^ tg) << 2));
#pragma unroll
            for (int c = 0; c < 4; c++)
                b[c] = *reinterpret_cast<const ulonglong2*>(
                    k_s + (rr * 4 + c) * 64 + e0);
#pragma unroll
            for (int i = 0; i < 4; i++) {
                u64 p;
                p = pk2(a[i].x); fma2(acc[i][0], p, b[0].x); fma2(acc[i][1], p, b[0].y);
                p = pk2(a[i].y); fma2(acc[i][0], p, b[1].x); fma2(acc[i][1], p, b[1].y);
                p = pk2(a[i].z); fma2(acc[i][0], p, b[2].x); fma2(acc[i][1], p, b[2].y);
                p = pk2(a[i].w); fma2(acc[i][0], p, b[3].x); fma2(acc[i][1], p, b[3].y);
            }
        }
#pragma unroll
        for (int mm = 0; mm < 16; mm++) {
            float4 a[4];
            ulonglong2 b[4];
#pragma unroll
            for (int i = 0; i < 4; i++) {
                int t = tg + 16 * i;
                a[i] = *reinterpret_cast<const float4*>(
                    A_s + t * 64 + ((mm ^ tg) << 2));
            }
#pragma unroll
            for (int c = 0; c < 4; c++)
                b[c] = *reinterpret_cast<const ulonglong2*>(
                    v_s + (mm * 4 + c) * 64 + e0);
#pragma unroll
            for (int i = 0; i < 4; i++) {
                u64 p;
                p = pk2(a[i].x); fma2(acc[i][0], p, b[0].x); fma2(acc[i][1], p, b[0].y);
                p = pk2(a[i].y); fma2(acc[i][0], p, b[1].x); fma2(acc[i][1], p, b[1].y);
                p = pk2(a[i].z); fma2(acc[i][0], p, b[2].x); fma2(acc[i][1], p, b[2].y);
                p = pk2(a[i].w); fma2(acc[i][0], p, b[3].x); fma2(acc[i][1], p, b[3].y);
            }
        }
        float* og = out + (size_t)tile * (C_ * D_);
#pragma unroll
        for (int i = 0; i < 4; i++) {
            int t = tg + 16 * i;
            float di = sDi[t];
            float2 h0 = up2(acc[i][0]), h1 = up2(acc[i][1]);
            *reinterpret_cast<float4*>(og + t * 64 + e0) =
                make_float4(h0.x * di, h0.y * di, h1.x * di, h1.y * di);
        }
    }
}

// ---------------------------------------------------------------------------
extern "C" void kernel_launch(void* const* d_in, const int* in_sizes, int n_in,
                              void* d_out, int out_size) {
    const float* q    = (const float*)d_in[0];
    const float* k    = (const float*)d_in[1];
    const float* v    = (const float*)d_in[2];
    const float* proj = (const float*)d_in[3];
    float* out = (float*)d_out;

    const int SMEM_F = (16384 + 64 * 68 + 64 + 8) * 4;
    const int SMEM_C = (16384 + 4096) * 4;
    const int SMEM_O = (16384 * 2 + 4096 + 4096 + 256 + 64 + 64) * 4;

    cudaFuncSetAttribute(k_feat<true>,  cudaFuncAttributeMaxDynamicSharedMemorySize, SMEM_F);
    cudaFuncSetAttribute(k_feat<false>, cudaFuncAttributeMaxDynamicSharedMemorySize, SMEM_F);
    cudaFuncSetAttribute(k_chunk,       cudaFuncAttributeMaxDynamicSharedMemorySize, SMEM_C);
    cudaFuncSetAttribute(k_out,         cudaFuncAttributeMaxDynamicSharedMemorySize, SMEM_O);

    k_prep<<<1, 256>>>(proj);
    k_feat<true><<<NTILES, 256, SMEM_F>>>(q);
    k_feat<false><<<NTILES, 256, SMEM_F>>>(k);
    k_chunk<<<NTILES, 256, SMEM_C>>>(v);
    k_scan<<<1040, 256>>>();
    k_out<<<NTILES, 256, SMEM_O>>>(v, out);
}